// round 5
// baseline (speedup 1.0000x reference)
#include <cuda_runtime.h>

// out[0, z, r, c, ch] = in[0, z_idx[z], row_idx[r], col_idx[c], 0]
// in (1,128,128,128,32) f32; idx arrays 64 x int32; out (1,64,64,64,32) f32.
//
// Block = 256 contiguous output voxels (32 KB of output).
// Phase 1: one gather per thread -> smem[256]  (4 global loads/thread total).
// Phase 2: 8 x (conflict-free LDS broadcast -> contiguous STG.128).
//          Store stream depends only on shared memory, not on DRAM latency.

__global__ __launch_bounds__(256) void sd3d_kernel(
    const float* __restrict__ in,
    const int*   __restrict__ z_idx,
    const int*   __restrict__ row_idx,
    const int*   __restrict__ col_idx,
    float4*      __restrict__ out)
{
    __shared__ float vals[256];

    int tid = threadIdx.x;
    int v = blockIdx.x * 256 + tid;       // voxel id, 0 .. 64^3-1
    int c = v & 63;
    int r = (v >> 6) & 63;
    int z = v >> 12;

    int zz = __ldg(z_idx + z);            // warp-uniform
    int rr = __ldg(row_idx + r);          // warp-uniform
    int cc = __ldg(col_idx + c);

    vals[tid] = __ldg(in + ((((long)zz * 128 + rr) * 128 + cc) << 5));
    __syncthreads();

    float4* o = out + (size_t)blockIdx.x * 2048;   // 256 voxels * 8 float4

#pragma unroll
    for (int i = 0; i < 8; i++) {
        // lanes 8k..8k+7 read the same word -> L1 broadcast, 4 distinct
        // consecutive words per warp instruction: conflict-free.
        float x = vals[(i * 256 + tid) >> 3];
        o[i * 256 + tid] = make_float4(x, x, x, x);   // warp: contiguous 512B
    }
}

extern "C" void kernel_launch(void* const* d_in, const int* in_sizes, int n_in,
                              void* d_out, int out_size)
{
    const float* in      = (const float*)d_in[0];
    const int*   z_idx   = (const int*)d_in[1];
    const int*   row_idx = (const int*)d_in[2];
    const int*   col_idx = (const int*)d_in[3];
    float4* out = (float4*)d_out;

    const int n_vox = 64 * 64 * 64;         // 262144
    const int threads = 256;
    const int blocks = n_vox / threads;     // 1024
    sd3d_kernel<<<blocks, threads>>>(in, z_idx, row_idx, col_idx, out);
}